// round 7
// baseline (speedup 1.0000x reference)
#include <cuda_runtime.h>
#include <cuda_bf16.h>
#include <cstdint>

#define NPTS 4096
#define NROWS_TOT 16384
#define INV_RENORM (1.0f / 1.004096f)
#define NEG_HALF_L2E (-0.72134752f)
#define L2E (1.44269504f)

// degree-4 poly of 24000*exp(x) on [0,1], abs err ~1 count
#define PA0 24000.62f
#define PA1 23969.11f
#define PA2 12239.55f
#define PA3 3359.48f
#define PA4 1669.28f

#define ASTR 72
#define BSTR 72
#define NSTR 264

// ---- device-global scratch ----
__device__ __align__(16) unsigned short g_zhi[NROWS_TOT * 64];
__device__ __align__(16) unsigned short g_zlo[NROWS_TOT * 64];
__device__ __align__(16) float          g_sq [NROWS_TOT];      // pre-scaled by -log2e/2
__device__ __align__(16) unsigned short g_num[(size_t)NROWS_TOT * NPTS];
__device__ __align__(16) float          g_scale[NROWS_TOT];

// ---- shared PTX helpers ----
__device__ __forceinline__ void ldsm_x4(uint32_t addr, uint32_t* r) {
    asm volatile("ldmatrix.sync.aligned.m8n8.x4.shared.b16 {%0,%1,%2,%3}, [%4];"
                 : "=r"(r[0]), "=r"(r[1]), "=r"(r[2]), "=r"(r[3]) : "r"(addr));
}
__device__ __forceinline__ void ldsm_x2(uint32_t addr, uint32_t* r) {
    asm volatile("ldmatrix.sync.aligned.m8n8.x2.shared.b16 {%0,%1}, [%2];"
                 : "=r"(r[0]), "=r"(r[1]) : "r"(addr));
}
__device__ __forceinline__ void mma_bf16(float* d, const uint32_t* a, const uint32_t* b) {
    asm volatile(
        "mma.sync.aligned.m16n8k16.row.col.f32.bf16.bf16.f32 "
        "{%0,%1,%2,%3},{%4,%5,%6,%7},{%8,%9},{%0,%1,%2,%3};"
        : "+f"(d[0]), "+f"(d[1]), "+f"(d[2]), "+f"(d[3])
        : "r"(a[0]), "r"(a[1]), "r"(a[2]), "r"(a[3]), "r"(b[0]), "r"(b[1]));
}
__device__ __forceinline__ void cp16(uint32_t dst, const void* src) {
    asm volatile("cp.async.cg.shared.global [%0], [%1], 16;" :: "r"(dst), "l"(src));
}
__device__ __forceinline__ void cp4(uint32_t dst, const void* src) {
    asm volatile("cp.async.ca.shared.global [%0], [%1], 4;" :: "r"(dst), "l"(src));
}
__device__ __forceinline__ void cp_commit() { asm volatile("cp.async.commit_group;"); }
__device__ __forceinline__ void cp_wait()   { asm volatile("cp.async.wait_group 0;"); }

__device__ __forceinline__ void bsplit(float v, unsigned short& h, unsigned short& l) {
    __nv_bfloat16 hh = __float2bfloat16(v);
    float hf = __bfloat162float(hh);
    __nv_bfloat16 ll = __float2bfloat16(v - hf);
    h = __bfloat16_as_ushort(hh);
    l = __bfloat16_as_ushort(ll);
}
__device__ __forceinline__ uint32_t smem_u32(const void* p) {
    uint32_t a;
    asm("{ .reg .u64 tt; cvta.to.shared.u64 tt, %1; cvt.u32.u64 %0, tt; }" : "=r"(a) : "l"(p));
    return a;
}

// ===========================================================================
// Kernel 1: MLP. Layer 1 (256->128) on tensor cores via bf16 split; layers
// 2/3 scalar. 64 rows/CTA, 512 threads, grid 256. smem 202,752 B.
// Layout: AHI [64][264]bf16 @0        (33792)   -> h1 overlay f32[64][128]
//         ALO [64][264]bf16 @33792    (33792)   -> h2 overlay f32[64][64]
//         WHI [128][264]bf16 @67584   (67584)   -> z  overlay f32[64][52]
//         WLO [128][264]bf16 @135168  (67584)
// ===========================================================================
#define MOFF_AHI 0
#define MOFF_ALO 33792
#define MOFF_WHI 67584
#define MOFF_WLO 135168
#define MLP_SMEM 202752

__global__ __launch_bounds__(512) void mlp_kernel(
    const float* __restrict__ emb,
    const float* __restrict__ W1, const float* __restrict__ b1,
    const float* __restrict__ W2, const float* __restrict__ b2,
    const float* __restrict__ W3, const float* __restrict__ b3)
{
    extern __shared__ char msm[];
    const uint32_t smu = smem_u32(msm);
    const int t = threadIdx.x;
    const int lane = t & 31, warp = t >> 5;
    const size_t rowbase = (size_t)blockIdx.x * 64;

    // ---- stage E (64x256) as bf16 split into AHI/ALO ----
    {
        const int row = t >> 3;              // 0..63
        const int c0  = (t & 7) * 32;        // 8 float4 per thread
        const float4* esrc = (const float4*)(emb + (rowbase + row) * 256 + c0);
        #pragma unroll
        for (int j = 0; j < 8; j++) {
            float4 v = esrc[j];
            ushort4 h4, l4;
            bsplit(v.x, h4.x, l4.x); bsplit(v.y, h4.y, l4.y);
            bsplit(v.z, h4.z, l4.z); bsplit(v.w, h4.w, l4.w);
            const int o = (row * 264 + c0 + j * 4) * 2;
            *(ushort4*)(msm + MOFF_AHI + o) = h4;
            *(ushort4*)(msm + MOFF_ALO + o) = l4;
        }
    }
    // ---- stage W1^T (128 f x 256 d) as bf16 split into WHI/WLO ----
    {
        const int f0 = (t & 31) * 4;
        const int d0 = t >> 5;               // 0..15
        #pragma unroll
        for (int it = 0; it < 16; it++) {
            const int d = d0 + it * 16;
            float4 w = *(const float4*)(W1 + d * 128 + f0);
            const float wv[4] = {w.x, w.y, w.z, w.w};
            #pragma unroll
            for (int j = 0; j < 4; j++) {
                unsigned short h, l;
                bsplit(wv[j], h, l);
                const int o = ((f0 + j) * 264 + d) * 2;
                *(unsigned short*)(msm + MOFF_WHI + o) = h;
                *(unsigned short*)(msm + MOFF_WLO + o) = l;
            }
        }
    }
    __syncthreads();

    // ---- layer 1 mma: 64x128, K=256, 3 split terms ----
    float acc[4][4];
    #pragma unroll
    for (int ms = 0; ms < 4; ms++)
        #pragma unroll
        for (int q = 0; q < 4; q++) acc[ms][q] = 0.f;

    const int a_lr = (lane & 7) + ((lane >> 3) & 1) * 8;
    const int a_lc = (lane >> 4) * 8;
    const int b_lr = warp * 8 + (lane & 7);
    const int b_lc = ((lane >> 3) & 1) * 8;

    #pragma unroll 4
    for (int ks = 0; ks < 16; ks++) {
        const int kk = ks * 16;
        uint32_t bh[2], bl[2];
        const uint32_t bo = (b_lr * 264 + kk + b_lc) * 2;
        ldsm_x2(smu + MOFF_WHI + bo, bh);
        ldsm_x2(smu + MOFF_WLO + bo, bl);
        #pragma unroll
        for (int ms = 0; ms < 4; ms++) {
            uint32_t ah[4], al[4];
            const uint32_t ao = ((ms * 16 + a_lr) * 264 + kk + a_lc) * 2;
            ldsm_x4(smu + MOFF_AHI + ao, ah);
            ldsm_x4(smu + MOFF_ALO + ao, al);
            mma_bf16(acc[ms], ah, bh);
            mma_bf16(acc[ms], ah, bl);
            mma_bf16(acc[ms], al, bh);
        }
    }
    __syncthreads();   // all ldsm done; AHI/ALO/W* reusable

    // ---- h1 = relu(acc + b1) -> overlay on AHI ----
    {
        float (*h1_s)[128] = (float(*)[128])(msm + MOFF_AHI);
        const int gr = lane >> 2;
        const int hc = warp * 8 + (lane & 3) * 2;
        const float bb0 = b1[hc], bb1 = b1[hc + 1];
        #pragma unroll
        for (int ms = 0; ms < 4; ms++) {
            const int r = ms * 16 + gr;
            h1_s[r][hc]       = fmaxf(acc[ms][0] + bb0, 0.f);
            h1_s[r][hc + 1]   = fmaxf(acc[ms][1] + bb1, 0.f);
            h1_s[r + 8][hc]     = fmaxf(acc[ms][2] + bb0, 0.f);
            h1_s[r + 8][hc + 1] = fmaxf(acc[ms][3] + bb1, 0.f);
        }
    }
    __syncthreads();

    // ---- layer 2: 128 -> 64, relu (scalar) ----
    {
        float (*h1_s)[128] = (float(*)[128])(msm + MOFF_AHI);
        float (*h2_s)[64]  = (float(*)[64]) (msm + MOFF_ALO);
        const int f = t & 63, rg = (t >> 6) * 8;
        float a2[8];
        #pragma unroll
        for (int r = 0; r < 8; r++) a2[r] = 0.f;
        const float* w = W2 + f;
        #pragma unroll 2
        for (int d = 0; d < 128; d += 4) {
            float w0 = w[(d + 0) * 64], w1 = w[(d + 1) * 64];
            float w2 = w[(d + 2) * 64], w3 = w[(d + 3) * 64];
            #pragma unroll
            for (int r = 0; r < 8; r++) {
                float4 e = *(const float4*)&h1_s[rg + r][d];
                a2[r] = fmaf(e.x, w0, a2[r]); a2[r] = fmaf(e.y, w1, a2[r]);
                a2[r] = fmaf(e.z, w2, a2[r]); a2[r] = fmaf(e.w, w3, a2[r]);
            }
        }
        const float bb = b2[f];
        __syncthreads();   // h1 reads done before h2 overlay (ALO) writes? ALO unused since mma; safe anyway
        #pragma unroll
        for (int r = 0; r < 8; r++) h2_s[rg + r][f] = fmaxf(a2[r] + bb, 0.f);
    }
    __syncthreads();

    // ---- layer 3: 64 -> 50 (scalar) ----
    {
        float (*h2_s)[64] = (float(*)[64])(msm + MOFF_ALO);
        float (*z_s)[52]  = (float(*)[52])(msm + MOFF_WHI);
        const int f = t & 63, rg = (t >> 6) * 8;
        if (f < 50) {
            float a3[8];
            #pragma unroll
            for (int r = 0; r < 8; r++) a3[r] = 0.f;
            const float* w = W3 + f;
            #pragma unroll
            for (int d = 0; d < 64; d += 4) {
                float w0 = w[(d + 0) * 50], w1 = w[(d + 1) * 50];
                float w2 = w[(d + 2) * 50], w3 = w[(d + 3) * 50];
                #pragma unroll
                for (int r = 0; r < 8; r++) {
                    float4 e = *(const float4*)&h2_s[rg + r][d];
                    a3[r] = fmaf(e.x, w0, a3[r]); a3[r] = fmaf(e.y, w1, a3[r]);
                    a3[r] = fmaf(e.z, w2, a3[r]); a3[r] = fmaf(e.w, w3, a3[r]);
                }
            }
            const float bb = b3[f];
            #pragma unroll
            for (int r = 0; r < 8; r++) z_s[rg + r][f] = a3[r] + bb;
        }
    }
    __syncthreads();

    // ---- z bf16-split write (pad 50->64) + scaled sq norms ----
    {
        float (*z_s)[52] = (float(*)[52])(msm + MOFF_WHI);
        const int zr = t >> 3;            // 0..63
        const int k0 = (t & 7) * 8;       // 8 k per thread
        ushort4 h4a, l4a, h4b, l4b;
        unsigned short* hp = &h4a.x;
        unsigned short* lp = &l4a.x;
        #pragma unroll
        for (int j = 0; j < 8; j++) {
            const int k = k0 + j;
            float v = (k < 50) ? z_s[zr][k] : 0.f;
            unsigned short h, l;
            bsplit(v, h, l);
            if (j < 4) { hp[j] = h; lp[j] = l; }
            else       { (&h4b.x)[j - 4] = h; (&l4b.x)[j - 4] = l; }
        }
        const size_t base = ((rowbase + zr) << 6) + k0;
        *(ushort4*)(g_zhi + base)     = h4a;
        *(ushort4*)(g_zlo + base)     = l4a;
        *(ushort4*)(g_zhi + base + 4) = h4b;
        *(ushort4*)(g_zlo + base + 4) = l4b;
    }
    if (t < 64) {
        float (*z_s)[52] = (float(*)[52])(msm + MOFF_WHI);
        float s2 = 0.f;
        #pragma unroll
        for (int k = 0; k < 50; k++) s2 = fmaf(z_s[t][k], z_s[t][k], s2);
        g_sq[rowbase + t] = NEG_HALF_L2E * s2;
    }
}

// ===========================================================================
// Kernel 2: gram, 64 rows x 4096 cols per CTA, 512 threads (16 warps),
// 16 tiles of 256 cols. smem 127,488 B, 1 CTA/SM.
// ===========================================================================
#define OFF_BHI 0
#define OFF_BLO 36864
#define OFF_AHI 73728
#define OFF_ALO 82944
#define OFF_NUM 92160
#define OFF_SQC 125952
#define OFF_SQR 126976
#define OFF_RSUM 127232
#define GRAM_SMEM 127488

__device__ __forceinline__ unsigned qexp(float arg) {
    float k;
    asm("ex2.approx.ftz.f32 %0, %1;" : "=f"(k) : "f"(arg));
    float p = fmaf(k, PA4, PA3);
    p = fmaf(k, p, PA2);
    p = fmaf(k, p, PA1);
    p = fmaf(k, p, PA0);
    return __float2uint_rn(p);
}

__global__ __launch_bounds__(512) void gram_kernel()
{
    extern __shared__ char sm[];
    const uint32_t smu = smem_u32(sm);

    float* sqp_c = (float*)(sm + OFF_SQC);
    float* sqp_r = (float*)(sm + OFF_SQR);
    int*   rsum  = (int*)  (sm + OFF_RSUM);

    const int t    = threadIdx.x;
    const int lane = t & 31, warp = t >> 5;
    const int b    = blockIdx.x >> 6;
    const int r0   = (blockIdx.x & 63) * 64;
    const int gr   = lane >> 2;

    // ---- load A (64 rows, hi+lo) + sqp_r + init rowsum ----
    {
        const int row = t >> 3, seg = t & 7;     // 512 = 64*8 exactly
        const size_t src = ((size_t)(b * NPTS + r0 + row) << 6) + seg * 8;
        const int dsto = (row * ASTR + seg * 8) * 2;
        *(uint4*)(sm + OFF_AHI + dsto) = *(const uint4*)(g_zhi + src);
        *(uint4*)(sm + OFF_ALO + dsto) = *(const uint4*)(g_zlo + src);
    }
    if (t < 64) { sqp_r[t] = g_sq[b * NPTS + r0 + t]; rsum[t] = 0; }

    // ---- prologue: cp.async tile 0 ----
    {
        const int row = t >> 3, seg = t & 7;
        #pragma unroll
        for (int i = 0; i < 4; i++) {
            const int rr = row + i * 64;
            const size_t src = ((size_t)(b * NPTS + rr) << 6) + seg * 8;
            const uint32_t dsto = (rr * BSTR + seg * 8) * 2;
            cp16(smu + OFF_BHI + dsto, g_zhi + src);
            cp16(smu + OFF_BLO + dsto, g_zlo + src);
        }
        if (t < 256) cp4(smu + OFF_SQC + t * 4, g_sq + b * NPTS + t);
        cp_commit();
    }

    const int a_lr = (lane & 7) + ((lane >> 3) & 1) * 8;
    const int a_lc = (lane >> 4) * 8;
    const int b_lr = warp * 16 + (lane & 7) + ((lane >> 4) & 1) * 8;
    const int b_lc = ((lane >> 3) & 1) * 8;

    for (int tile = 0; tile < 16; tile++) {
        const int col0 = tile * 256;
        cp_wait();
        __syncthreads();

        // ---- mma: 64x256 tile, 3 split terms ----
        float acc[4][2][4];
        #pragma unroll
        for (int ms = 0; ms < 4; ms++)
            #pragma unroll
            for (int ns = 0; ns < 2; ns++)
                #pragma unroll
                for (int q = 0; q < 4; q++) acc[ms][ns][q] = 0.f;

        #pragma unroll
        for (int ks = 0; ks < 4; ks++) {
            const int kk = ks * 16;
            uint32_t bfh[4], bfl[4];
            const uint32_t bo = (b_lr * BSTR + kk + b_lc) * 2;
            ldsm_x4(smu + OFF_BHI + bo, bfh);
            ldsm_x4(smu + OFF_BLO + bo, bfl);
            #pragma unroll
            for (int ms = 0; ms < 4; ms++) {
                uint32_t afh[4], afl[4];
                const uint32_t ao = ((ms * 16 + a_lr) * ASTR + kk + a_lc) * 2;
                ldsm_x4(smu + OFF_AHI + ao, afh);
                ldsm_x4(smu + OFF_ALO + ao, afl);
                mma_bf16(acc[ms][0], afh, &bfh[0]);
                mma_bf16(acc[ms][1], afh, &bfh[2]);
                mma_bf16(acc[ms][0], afh, &bfl[0]);
                mma_bf16(acc[ms][1], afh, &bfl[2]);
                mma_bf16(acc[ms][0], afl, &bfh[0]);
                mma_bf16(acc[ms][1], afl, &bfh[2]);
            }
        }

        // ---- epilogue -> u16 numerators staged to smem ----
        #pragma unroll
        for (int ms = 0; ms < 4; ms++) {
            const int ra = ms * 16 + gr;
            const float rr0 = sqp_r[ra], rr1 = sqp_r[ra + 8];
            #pragma unroll
            for (int ns = 0; ns < 2; ns++) {
                const int col = warp * 16 + ns * 8 + (lane & 3) * 2;
                const float sc0 = sqp_c[col], sc1 = sqp_c[col + 1];
                unsigned u0 = qexp(fmaf(L2E, acc[ms][ns][0], rr0 + sc0));
                unsigned u1 = qexp(fmaf(L2E, acc[ms][ns][1], rr0 + sc1));
                unsigned u2 = qexp(fmaf(L2E, acc[ms][ns][2], rr1 + sc0));
                unsigned u3 = qexp(fmaf(L2E, acc[ms][ns][3], rr1 + sc1));
                *(uint32_t*)(sm + OFF_NUM + (ra * NSTR + col) * 2)       = u0 | (u1 << 16);
                *(uint32_t*)(sm + OFF_NUM + ((ra + 8) * NSTR + col) * 2) = u2 | (u3 << 16);
            }
        }
        __syncthreads();

        // ---- prefetch next tile ----
        if (tile < 15) {
            const int row = t >> 3, seg = t & 7;
            #pragma unroll
            for (int i = 0; i < 4; i++) {
                const int rr = row + i * 64;
                const size_t src = ((size_t)(b * NPTS + col0 + 256 + rr) << 6) + seg * 8;
                const uint32_t dsto = (rr * BSTR + seg * 8) * 2;
                cp16(smu + OFF_BHI + dsto, g_zhi + src);
                cp16(smu + OFF_BLO + dsto, g_zlo + src);
            }
            if (t < 256) cp4(smu + OFF_SQC + t * 4, g_sq + b * NPTS + col0 + 256 + t);
        }
        cp_commit();

        // ---- copy-out 64x256 u16 tile + integer rowsums ----
        {
            const int row = t >> 3, cbase = (t & 7) * 32;
            unsigned short* gdst = g_num +
                ((size_t)(b * NPTS + r0 + row) << 12) + col0 + cbase;
            int s = 0;
            #pragma unroll
            for (int j = 0; j < 4; j++) {
                uint4 v = *(const uint4*)(sm + OFF_NUM + (row * NSTR + cbase + j * 8) * 2);
                s += (int)(v.x & 0xFFFFu) + (int)(v.x >> 16);
                s += (int)(v.y & 0xFFFFu) + (int)(v.y >> 16);
                s += (int)(v.z & 0xFFFFu) + (int)(v.z >> 16);
                s += (int)(v.w & 0xFFFFu) + (int)(v.w >> 16);
                *(uint4*)(gdst + j * 8) = v;
            }
            s += __shfl_xor_sync(0xFFFFFFFFu, s, 1);
            s += __shfl_xor_sync(0xFFFFFFFFu, s, 2);
            s += __shfl_xor_sync(0xFFFFFFFFu, s, 4);
            if ((lane & 7) == 0) atomicAdd(&rsum[row], s);
        }
    }

    __syncthreads();
    if (t < 64)
        g_scale[b * NPTS + r0 + t] = INV_RENORM / (float)rsum[t];
}

// ===========================================================================
// Kernel 3: rescale u16 numerators -> float output.
// ===========================================================================
__global__ __launch_bounds__(256) void rescale_kernel(float* __restrict__ out)
{
    const size_t idx = (size_t)blockIdx.x * 256 + threadIdx.x;
    const size_t row = idx >> 9;
    const uint4 v = ((const uint4*)g_num)[idx];
    const float s = g_scale[row];
    const float bias = 1e-6f * INV_RENORM;
    float4 o0, o1;
    o0.x = fmaf((float)(v.x & 0xFFFFu), s, bias);
    o0.y = fmaf((float)(v.x >> 16),     s, bias);
    o0.z = fmaf((float)(v.y & 0xFFFFu), s, bias);
    o0.w = fmaf((float)(v.y >> 16),     s, bias);
    o1.x = fmaf((float)(v.z & 0xFFFFu), s, bias);
    o1.y = fmaf((float)(v.z >> 16),     s, bias);
    o1.z = fmaf((float)(v.w & 0xFFFFu), s, bias);
    o1.w = fmaf((float)(v.w >> 16),     s, bias);
    ((float4*)out)[idx * 2]     = o0;
    ((float4*)out)[idx * 2 + 1] = o1;
}

// ===========================================================================
extern "C" void kernel_launch(void* const* d_in, const int* in_sizes, int n_in,
                              void* d_out, int out_size)
{
    const float* emb = (const float*)d_in[0];
    const float* W1  = (const float*)d_in[1];
    const float* b1  = (const float*)d_in[2];
    const float* W2  = (const float*)d_in[3];
    const float* b2  = (const float*)d_in[4];
    const float* W3  = (const float*)d_in[5];
    const float* b3  = (const float*)d_in[6];
    float* out = (float*)d_out;

    cudaFuncSetAttribute(mlp_kernel,  cudaFuncAttributeMaxDynamicSharedMemorySize, MLP_SMEM);
    cudaFuncSetAttribute(gram_kernel, cudaFuncAttributeMaxDynamicSharedMemorySize, GRAM_SMEM);

    mlp_kernel<<<256, 512, MLP_SMEM>>>(emb, W1, b1, W2, b2, W3, b3);
    gram_kernel<<<256, 512, GRAM_SMEM>>>();
    rescale_kernel<<<32768, 256>>>(out);
}